// round 8
// baseline (speedup 1.0000x reference)
#include <cuda_runtime.h>
#include <cuda_fp16.h>
#include <cstdint>

// ============================================================================
// out[m,b,o] = relu( sum_i inp[m,b,i] * w[m,i,o] + bias[m,o] )
// M=8, B=4096, D_IN=512, D_OUT=512, fp32.
//
// R8: revert to fp16-everywhere datapath (ldmatrix A and B), scale CTA to
//     128x256 with 8 warps (2x4) of 64x64 warp tiles -> 16 warps/SM at
//     2 CTAs/SM (4 per SMSP) for latency hiding. KC=64, NSTAGE=2 (108KB),
//     fragment double-buffering, fused bias+relu epilogue.
// ============================================================================

static constexpr int MDIM = 8;
static constexpr int BDIM = 4096;
static constexpr int DIN  = 512;
static constexpr int DOUT = 512;

static constexpr int BM = 128;
static constexpr int BN = 256;
static constexpr int KC = 64;              // K per pipeline chunk
static constexpr int NCHUNK = DIN / KC;    // 8
static constexpr int NSTAGE = 2;
static constexpr int THREADS = 256;        // 8 warps, 2x4 grid of 64x64 tiles

// SMEM rows: 64 halves (128B data) padded to 144B -> ldmatrix conflict-free,
// 16B-aligned for cp.async.
static constexpr int ROWB = 144;
static constexpr int A_REGION = BM * ROWB;             // 18432
static constexpr int B_REGION = BN * ROWB;             // 36864
static constexpr int STAGE_BYTES = A_REGION + B_REGION;    // 55296
static constexpr int SMEM_TOTAL  = NSTAGE * STAGE_BYTES;   // 110592

// fp16 scratch (static device globals; no runtime allocation)
__device__ __align__(16) __half g_Ah[(size_t)MDIM * BDIM * DIN];   // 32 MB
__device__ __align__(16) __half g_Bh[(size_t)MDIM * DOUT * DIN];   // 4 MB

// ---------------- helpers ----------------

__device__ __forceinline__ uint32_t smem_u32(const void* p) {
    uint32_t a;
    asm("{ .reg .u64 t; cvta.to.shared.u64 t, %1; cvt.u32.u64 %0, t; }"
        : "=r"(a) : "l"(p));
    return a;
}

__device__ __forceinline__ void cp16(uint32_t dst, const void* src) {
    asm volatile("cp.async.cg.shared.global [%0], [%1], 16;"
                 :: "r"(dst), "l"(src) : "memory");
}

__device__ __forceinline__ void ldmx4(uint32_t* r, uint32_t addr) {
    asm volatile("ldmatrix.sync.aligned.m8n8.x4.shared.b16 {%0,%1,%2,%3}, [%4];"
                 : "=r"(r[0]), "=r"(r[1]), "=r"(r[2]), "=r"(r[3]) : "r"(addr));
}

__device__ __forceinline__ void mma_f16(float* c, const uint32_t* a,
                                        const uint32_t* b) {
    asm volatile(
        "mma.sync.aligned.m16n8k16.row.col.f32.f16.f16.f32 "
        "{%0,%1,%2,%3}, {%4,%5,%6,%7}, {%8,%9}, {%0,%1,%2,%3};"
        : "+f"(c[0]), "+f"(c[1]), "+f"(c[2]), "+f"(c[3])
        : "r"(a[0]), "r"(a[1]), "r"(a[2]), "r"(a[3]),
          "r"(b[0]), "r"(b[1]));
}

// ---------------- preprocessing ----------------

// inp fp32 -> g_Ah fp16 (same layout). MLP=4 (best measured variant).
__global__ void __launch_bounds__(256) convert_a_kernel(const float4* __restrict__ in) {
    const size_t base = (size_t)blockIdx.x * 1024 + threadIdx.x;
    float4 v[4];
#pragma unroll
    for (int k = 0; k < 4; ++k) v[k] = in[base + k * 256];
#pragma unroll
    for (int k = 0; k < 4; ++k) {
        __half2 h0 = __floats2half2_rn(v[k].x, v[k].y);
        __half2 h1 = __floats2half2_rn(v[k].z, v[k].w);
        uint2 st;
        st.x = *reinterpret_cast<uint32_t*>(&h0);
        st.y = *reinterpret_cast<uint32_t*>(&h1);
        reinterpret_cast<uint2*>(g_Ah)[base + k * 256] = st;
    }
}

// w[m][i][o] fp32 -> g_Bh[m][o][i] fp16 (transpose + convert)
__global__ void __launch_bounds__(256) convert_w_kernel(const float* __restrict__ w) {
    __shared__ float tile[32][33];
    const int m  = blockIdx.z;
    const int o0 = blockIdx.x * 32;
    const int i0 = blockIdx.y * 32;
    const int tx = threadIdx.x;
    const int ty = threadIdx.y;
    const float* wm = w + (size_t)m * DIN * DOUT;
    __half* bm = g_Bh + (size_t)m * DOUT * DIN;
#pragma unroll
    for (int j = 0; j < 32; j += 8)
        tile[ty + j][tx] = wm[(size_t)(i0 + ty + j) * DOUT + o0 + tx];
    __syncthreads();
#pragma unroll
    for (int j = 0; j < 32; j += 8)
        bm[(size_t)(o0 + ty + j) * DIN + i0 + tx] = __float2half_rn(tile[tx][ty + j]);
}

// ---------------- main GEMM kernel ----------------

__global__ void __launch_bounds__(THREADS, 2)
fused_gemm_f16_kernel(const float* __restrict__ bias, float* __restrict__ out) {
    extern __shared__ char smem[];
    const uint32_t sbase = smem_u32(smem);

    const int tid  = threadIdx.x;
    const int warp = tid >> 5;
    const int lane = tid & 31;
    const int gid  = lane >> 2;
    const int tig  = lane & 3;
    const int wr   = warp >> 2;      // warp row (0..1) -> 64 rows
    const int wc   = warp & 3;       // warp col (0..3) -> 64 cols

    const int tn = blockIdx.x;       // D_OUT tile (0..1) — fastest: A reuse in L2
    const int tm = blockIdx.y;       // B-dim tile (0..31)
    const int mm = blockIdx.z;       // matrix (0..7)

    const __half* __restrict__ Ag = g_Ah + ((size_t)mm * BDIM + (size_t)tm * BM) * DIN;
    const __half* __restrict__ Bg = g_Bh + ((size_t)mm * DOUT + (size_t)tn * BN) * DIN;

    float acc[4][8][4];
#pragma unroll
    for (int mt = 0; mt < 4; ++mt)
#pragma unroll
        for (int nt = 0; nt < 8; ++nt)
#pragma unroll
            for (int i = 0; i < 4; ++i) acc[mt][nt][i] = 0.0f;

    // ---- async loader for chunk c into stage s: A 128x64h, B 256x64h
    auto issue_chunk = [&](int c, int s) {
        const uint32_t sA = sbase + s * STAGE_BYTES;
        const uint32_t sB = sA + A_REGION;
#pragma unroll
        for (int it = 0; it < 4; ++it) {
            int idx = tid + it * THREADS;        // 0..1023
            int row = idx >> 3;                  // 0..127
            int q   = idx & 7;                   // 16B eighth of 128B row
            cp16(sA + row * ROWB + q * 16, Ag + (size_t)row * DIN + c * KC + q * 8);
        }
#pragma unroll
        for (int it = 0; it < 8; ++it) {
            int idx = tid + it * THREADS;        // 0..2047
            int n = idx >> 3;                    // 0..255
            int q = idx & 7;
            cp16(sB + n * ROWB + q * 16, Bg + (size_t)n * DIN + c * KC + q * 8);
        }
        asm volatile("cp.async.commit_group;" ::: "memory");
    };

    // ---- per-lane ldmatrix base offsets (stage-relative)
    const uint32_t a_lane_off =
        (uint32_t)((wr * 64 + (lane & 15)) * ROWB + (lane >> 4) * 16);
    const uint32_t b_lane_off =
        (uint32_t)((wc * 64 + (lane & 7) + ((lane >> 4) << 3)) * ROWB +
                   ((lane >> 3) & 1) * 16);

    // ---- prologue
    issue_chunk(0, 0);

    // ---- main loop: one barrier per chunk, frag double-buffer inside
#pragma unroll 1
    for (int c = 0; c < NCHUNK; ++c) {
        asm volatile("cp.async.wait_group 0;" ::: "memory");
        __syncthreads();   // chunk c visible; all warps done with stage c-1

        const uint32_t sA = sbase + (c & 1) * STAGE_BYTES;
        const uint32_t sB = sA + A_REGION;

        // loads for chunk c+1 overlap this chunk's compute
        if (c + 1 < NCHUNK)
            issue_chunk(c + 1, (c + 1) & 1);

        uint32_t af[2][4][4], bf[2][4][4];

        // preload kstep 0
#pragma unroll
        for (int mt = 0; mt < 4; ++mt)
            ldmx4(af[0][mt], sA + a_lane_off + mt * (16 * ROWB));
#pragma unroll
        for (int p = 0; p < 4; ++p)
            ldmx4(bf[0][p], sB + b_lane_off + p * (16 * ROWB));

#pragma unroll
        for (int ks = 0; ks < 4; ++ks) {
            const int cur = ks & 1, nxt = cur ^ 1;
            if (ks < 3) {
                const uint32_t ko = (uint32_t)(ks + 1) * 32;   // 16 halves = 32B
#pragma unroll
                for (int mt = 0; mt < 4; ++mt)
                    ldmx4(af[nxt][mt], sA + a_lane_off + mt * (16 * ROWB) + ko);
#pragma unroll
                for (int p = 0; p < 4; ++p)
                    ldmx4(bf[nxt][p], sB + b_lane_off + p * (16 * ROWB) + ko);
            }
#pragma unroll
            for (int mt = 0; mt < 4; ++mt)
#pragma unroll
                for (int nt = 0; nt < 8; ++nt)
                    mma_f16(acc[mt][nt], af[cur][mt], &bf[cur][nt >> 1][(nt & 1) * 2]);
        }
    }

    // ---- epilogue: bias + relu, float2 stores
    const float* brow = bias + (size_t)mm * DOUT + tn * BN + wc * 64;
    float2 bv[8];
#pragma unroll
    for (int nt = 0; nt < 8; ++nt)
        bv[nt] = *reinterpret_cast<const float2*>(brow + nt * 8 + tig * 2);

#pragma unroll
    for (int mt = 0; mt < 4; ++mt) {
        const int r0 = tm * BM + wr * 64 + mt * 16 + gid;
        float* o0 = out + ((size_t)mm * BDIM + r0) * DOUT + tn * BN + wc * 64;
        float* o1 = o0 + 8 * DOUT;
#pragma unroll
        for (int nt = 0; nt < 8; ++nt) {
            float2 v0, v1;
            v0.x = fmaxf(acc[mt][nt][0] + bv[nt].x, 0.0f);
            v0.y = fmaxf(acc[mt][nt][1] + bv[nt].y, 0.0f);
            v1.x = fmaxf(acc[mt][nt][2] + bv[nt].x, 0.0f);
            v1.y = fmaxf(acc[mt][nt][3] + bv[nt].y, 0.0f);
            *reinterpret_cast<float2*>(o0 + nt * 8 + tig * 2) = v0;
            *reinterpret_cast<float2*>(o1 + nt * 8 + tig * 2) = v1;
        }
    }
}

// ---------------------------------------------------------------------------

extern "C" void kernel_launch(void* const* d_in, const int* in_sizes, int n_in,
                              void* d_out, int out_size) {
    const float* inp  = (const float*)d_in[0];   // [8, 4096, 512]
    const float* w    = (const float*)d_in[1];   // [8, 512, 512]
    const float* bias = (const float*)d_in[2];   // [8, 512]
    float* out = (float*)d_out;                  // [8, 4096, 512]
    (void)in_sizes; (void)n_in; (void)out_size;

    // 1) fp32 -> fp16 conversions
    const size_t n4 = (size_t)MDIM * BDIM * DIN / 4;     // 4,194,304 float4s
    convert_a_kernel<<<(unsigned)(n4 / 1024), 256>>>((const float4*)inp);
    convert_w_kernel<<<dim3(DOUT / 32, DIN / 32, MDIM), dim3(32, 8)>>>(w);

    // 2) fp16 tensor-core GEMM + bias + relu
    cudaFuncSetAttribute(fused_gemm_f16_kernel,
                         cudaFuncAttributeMaxDynamicSharedMemorySize, SMEM_TOTAL);
    dim3 grid(DOUT / BN, BDIM / BM, MDIM);   // (2, 32, 8) = 512 CTAs
    fused_gemm_f16_kernel<<<grid, THREADS, SMEM_TOTAL>>>(bias, out);
}

// round 9
// speedup vs baseline: 2.0668x; 2.0668x over previous
#include <cuda_runtime.h>
#include <cuda_fp16.h>
#include <cstdint>

// ============================================================================
// out[m,b,o] = relu( sum_i inp[m,b,i] * w[m,i,o] + bias[m,o] )
// M=8, B=4096, D_IN=512, D_OUT=512, fp32.
//
// R9: R6 GEMM datapath (4 warps, 2x2 of 64x64, ldmatrix+mma.m16n8k16,
//     KC=64, one barrier/chunk) with A-conversion FUSED store-side:
//     LDG.128 fp32 A for chunk c+1 (pipelined per k-step) -> cvt.rn.f16x2
//     -> STS into double-buffered fp16 A smem. No convert_a kernel.
//     B from 4MB fp16 transposed weights (convert_w) via cp.async.
// ============================================================================

static constexpr int MDIM = 8;
static constexpr int BDIM = 4096;
static constexpr int DIN  = 512;
static constexpr int DOUT = 512;

static constexpr int BM = 128;
static constexpr int BN = 128;
static constexpr int KC = 64;              // K per chunk
static constexpr int NCHUNK = DIN / KC;    // 8
static constexpr int THREADS = 128;        // 4 warps, 2x2 grid of 64x64 tiles

// fp16 smem rows: 64 halves (128B) padded to 144B -> ldmatrix conflict-free.
static constexpr int ROWB = 144;
static constexpr int A_BUF = BM * ROWB;    // 18432 (x2 buffers)
static constexpr int B_BUF = BN * ROWB;    // 18432 (x2 stages)
static constexpr int SMEM_TOTAL = 2 * A_BUF + 2 * B_BUF;   // 73728

// fp16 transposed weights scratch (4 MB; static device global)
__device__ __align__(16) __half g_Bh[(size_t)MDIM * DOUT * DIN];

// ---------------- helpers ----------------

__device__ __forceinline__ uint32_t smem_u32(const void* p) {
    uint32_t a;
    asm("{ .reg .u64 t; cvta.to.shared.u64 t, %1; cvt.u32.u64 %0, t; }"
        : "=r"(a) : "l"(p));
    return a;
}

__device__ __forceinline__ void cp16(uint32_t dst, const void* src) {
    asm volatile("cp.async.cg.shared.global [%0], [%1], 16;"
                 :: "r"(dst), "l"(src) : "memory");
}

__device__ __forceinline__ void ldmx4(uint32_t* r, uint32_t addr) {
    asm volatile("ldmatrix.sync.aligned.m8n8.x4.shared.b16 {%0,%1,%2,%3}, [%4];"
                 : "=r"(r[0]), "=r"(r[1]), "=r"(r[2]), "=r"(r[3]) : "r"(addr));
}

// pack (f0 -> lo, f1 -> hi)
__device__ __forceinline__ uint32_t pack_h2(float f0, float f1) {
    uint32_t d;
    asm("cvt.rn.f16x2.f32 %0, %2, %1;" : "=r"(d) : "f"(f0), "f"(f1));
    return d;
}

__device__ __forceinline__ void sts64(uint32_t addr, uint32_t lo, uint32_t hi) {
    asm volatile("st.shared.v2.b32 [%0], {%1,%2};" :: "r"(addr), "r"(lo), "r"(hi)
                 : "memory");
}

__device__ __forceinline__ void mma_f16(float* c, const uint32_t* a,
                                        const uint32_t* b) {
    asm volatile(
        "mma.sync.aligned.m16n8k16.row.col.f32.f16.f16.f32 "
        "{%0,%1,%2,%3}, {%4,%5,%6,%7}, {%8,%9}, {%0,%1,%2,%3};"
        : "+f"(c[0]), "+f"(c[1]), "+f"(c[2]), "+f"(c[3])
        : "r"(a[0]), "r"(a[1]), "r"(a[2]), "r"(a[3]),
          "r"(b[0]), "r"(b[1]));
}

// ---------------- preprocessing: w[m][i][o] fp32 -> g_Bh[m][o][i] fp16 -------

__global__ void __launch_bounds__(256) convert_w_kernel(const float* __restrict__ w) {
    __shared__ float tile[32][33];
    const int m  = blockIdx.z;
    const int o0 = blockIdx.x * 32;
    const int i0 = blockIdx.y * 32;
    const int tx = threadIdx.x;
    const int ty = threadIdx.y;
    const float* wm = w + (size_t)m * DIN * DOUT;
    __half* bm = g_Bh + (size_t)m * DOUT * DIN;
#pragma unroll
    for (int j = 0; j < 32; j += 8)
        tile[ty + j][tx] = wm[(size_t)(i0 + ty + j) * DOUT + o0 + tx];
    __syncthreads();
#pragma unroll
    for (int j = 0; j < 32; j += 8)
        bm[(size_t)(o0 + ty + j) * DIN + i0 + tx] = __float2half_rn(tile[tx][ty + j]);
}

// ---------------- main GEMM kernel ----------------

__global__ void __launch_bounds__(THREADS, 2)
fused_gemm_f16_kernel(const float* __restrict__ inp,
                      const float* __restrict__ bias,
                      float* __restrict__ out) {
    extern __shared__ char smem[];
    const uint32_t sbase = smem_u32(smem);
    const uint32_t sA0 = sbase;                  // fp16 A buffer 0
    const uint32_t sA1 = sbase + A_BUF;          // fp16 A buffer 1
    const uint32_t sB0 = sbase + 2 * A_BUF;      // fp16 B stage 0
    const uint32_t sB1 = sB0 + B_BUF;            // fp16 B stage 1

    const int tid  = threadIdx.x;
    const int warp = tid >> 5;
    const int lane = tid & 31;
    const int gid  = lane >> 2;
    const int tig  = lane & 3;
    const int wr   = warp >> 1;      // warp row (0..1) -> 64 rows
    const int wc   = warp & 1;       // warp col (0..1) -> 64 cols

    const int tn = blockIdx.x;       // D_OUT tile (0..3) — fastest: A reuse in L2
    const int tm = blockIdx.y;       // B-dim tile (0..31)
    const int mm = blockIdx.z;       // matrix (0..7)

    const float*  __restrict__ Ag = inp  + ((size_t)mm * BDIM + (size_t)tm * BM) * DIN;
    const __half* __restrict__ Bg = g_Bh + ((size_t)mm * DOUT + (size_t)tn * BN) * DIN;

    // per-thread A-convert mapping: iteration k of group g covers
    // row = 32*g + 8*k + (tid>>4), colf = (tid&15)*4  (coalesced LDG.128)
    const int a_row_base = tid >> 4;          // 0..7
    const int a_colf     = (tid & 15) * 4;    // 0..60
    const uint32_t a_sts_base = (uint32_t)(a_row_base * ROWB + (tid & 15) * 8);

    float acc[4][8][4];
#pragma unroll
    for (int mt = 0; mt < 4; ++mt)
#pragma unroll
        for (int nt = 0; nt < 8; ++nt)
#pragma unroll
            for (int i = 0; i < 4; ++i) acc[mt][nt][i] = 0.0f;

    // ---- B async loader for chunk c into stage
    auto issue_b = [&](int c, uint32_t sB) {
#pragma unroll
        for (int it = 0; it < 8; ++it) {
            int idx = tid + it * THREADS;        // 0..1023
            int n = idx >> 3;                    // 0..127
            int q = idx & 7;
            cp16(sB + n * ROWB + q * 16, Bg + (size_t)n * DIN + c * KC + q * 8);
        }
        asm volatile("cp.async.commit_group;" ::: "memory");
    };

    // A group LDG (4 float4s) / convert+store
    auto ldg_a_group = [&](float4* v, int c, int g) {
        const float* src = Ag + (size_t)(32 * g + a_row_base) * DIN + c * KC + a_colf;
#pragma unroll
        for (int k = 0; k < 4; ++k)
            v[k] = *reinterpret_cast<const float4*>(src + (size_t)(8 * k) * DIN);
    };
    auto sts_a_group = [&](const float4* v, uint32_t sA, int g) {
        const uint32_t dst = sA + a_sts_base + (uint32_t)(32 * g) * ROWB;
#pragma unroll
        for (int k = 0; k < 4; ++k)
            sts64(dst + (uint32_t)(8 * k) * ROWB,
                  pack_h2(v[k].x, v[k].y), pack_h2(v[k].z, v[k].w));
    };

    // ---- per-lane ldmatrix base offsets (buffer-relative)
    const uint32_t a_lane_off =
        (uint32_t)((wr * 64 + (lane & 15)) * ROWB + (lane >> 4) * 16);
    const uint32_t b_lane_off =
        (uint32_t)((wc * 64 + (lane & 7) + ((lane >> 4) << 3)) * ROWB +
                   ((lane >> 3) & 1) * 16);

    // ---- prologue: chunk 0 -> A buf0 (LDG+CVT+STS), B stage0 (cp.async)
    issue_b(0, sB0);
    {
        float4 v[4];
#pragma unroll
        for (int g = 0; g < 4; ++g) {
            ldg_a_group(v, 0, g);
            sts_a_group(v, sA0, g);
        }
    }

    // ---- main loop
#pragma unroll 1
    for (int c = 0; c < NCHUNK; ++c) {
        asm volatile("cp.async.wait_group 0;" ::: "memory");
        __syncthreads();   // chunk c A (STS) + B (cp.async) visible

        const uint32_t sA = (c & 1) ? sA1 : sA0;
        const uint32_t sB = (c & 1) ? sB1 : sB0;
        const uint32_t sAn = (c & 1) ? sA0 : sA1;
        const uint32_t sBn = (c & 1) ? sB0 : sB1;
        const bool pf = (c + 1 < NCHUNK);

        if (pf) issue_b(c + 1, sBn);

        uint32_t af[2][4][4], bf[2][4][4];
        float4 va[2][4];

        // preload kstep 0 fragments
#pragma unroll
        for (int mt = 0; mt < 4; ++mt)
            ldmx4(af[0][mt], sA + a_lane_off + mt * (16 * ROWB));
#pragma unroll
        for (int p = 0; p < 4; ++p)
            ldmx4(bf[0][p], sB + b_lane_off + p * (16 * ROWB));

#pragma unroll
        for (int ks = 0; ks < 4; ++ks) {
            const int cur = ks & 1, nxt = cur ^ 1;

            // issue LDG for A(c+1) group ks (converted at end of ks+1)
            if (pf) ldg_a_group(va[cur], c + 1, ks);

            if (ks < 3) {
                const uint32_t ko = (uint32_t)(ks + 1) * 32;   // 16 halves
#pragma unroll
                for (int mt = 0; mt < 4; ++mt)
                    ldmx4(af[nxt][mt], sA + a_lane_off + mt * (16 * ROWB) + ko);
#pragma unroll
                for (int p = 0; p < 4; ++p)
                    ldmx4(bf[nxt][p], sB + b_lane_off + p * (16 * ROWB) + ko);
            }
#pragma unroll
            for (int mt = 0; mt < 4; ++mt)
#pragma unroll
                for (int nt = 0; nt < 8; ++nt)
                    mma_f16(acc[mt][nt], af[cur][mt], &bf[cur][nt >> 1][(nt & 1) * 2]);

            // convert+store previous group (its LDG has had a full k-step)
            if (pf && ks >= 1) sts_a_group(va[nxt], sAn, ks - 1);
        }
        if (pf) sts_a_group(va[1], sAn, 3);   // last group (cur at ks=3 is 1)
    }

    // ---- epilogue: bias + relu, float2 stores
    const float* brow = bias + (size_t)mm * DOUT + tn * BN + wc * 64;
    float2 bv[8];
#pragma unroll
    for (int nt = 0; nt < 8; ++nt)
        bv[nt] = *reinterpret_cast<const float2*>(brow + nt * 8 + tig * 2);

#pragma unroll
    for (int mt = 0; mt < 4; ++mt) {
        const int r0 = tm * BM + wr * 64 + mt * 16 + gid;
        float* o0 = out + ((size_t)mm * BDIM + r0) * DOUT + tn * BN + wc * 64;
        float* o1 = o0 + 8 * DOUT;
#pragma unroll
        for (int nt = 0; nt < 8; ++nt) {
            float2 v0, v1;
            v0.x = fmaxf(acc[mt][nt][0] + bv[nt].x, 0.0f);
            v0.y = fmaxf(acc[mt][nt][1] + bv[nt].y, 0.0f);
            v1.x = fmaxf(acc[mt][nt][2] + bv[nt].x, 0.0f);
            v1.y = fmaxf(acc[mt][nt][3] + bv[nt].y, 0.0f);
            *reinterpret_cast<float2*>(o0 + nt * 8 + tig * 2) = v0;
            *reinterpret_cast<float2*>(o1 + nt * 8 + tig * 2) = v1;
        }
    }
}

// ---------------------------------------------------------------------------

extern "C" void kernel_launch(void* const* d_in, const int* in_sizes, int n_in,
                              void* d_out, int out_size) {
    const float* inp  = (const float*)d_in[0];   // [8, 4096, 512]
    const float* w    = (const float*)d_in[1];   // [8, 512, 512]
    const float* bias = (const float*)d_in[2];   // [8, 512]
    float* out = (float*)d_out;                  // [8, 4096, 512]
    (void)in_sizes; (void)n_in; (void)out_size;

    // 1) weights fp32 -> fp16 transposed [m][o][i] (4 MB)
    convert_w_kernel<<<dim3(DOUT / 32, DIN / 32, MDIM), dim3(32, 8)>>>(w);

    // 2) fused GEMM: A converted in-kernel, bias+relu epilogue
    cudaFuncSetAttribute(fused_gemm_f16_kernel,
                         cudaFuncAttributeMaxDynamicSharedMemorySize, SMEM_TOTAL);
    dim3 grid(DOUT / BN, BDIM / BM, MDIM);   // (4, 32, 8) = 1024 CTAs
    fused_gemm_f16_kernel<<<grid, THREADS, SMEM_TOTAL>>>(inp, bias, out);
}

// round 11
// speedup vs baseline: 2.1939x; 1.0615x over previous
#include <cuda_runtime.h>
#include <cuda_fp16.h>
#include <cstdint>

// ============================================================================
// out[m,b,o] = relu( sum_i inp[m,b,i] * w[m,i,o] + bias[m,o] )
// M=8, B=4096, D_IN=512, D_OUT=512, fp32.
//
// R11 (= R10 resubmitted after container infra failure):
//      high-occupancy GEMM — 8 warps/CTA (2x4) of 64x32 warp tiles,
//      SINGLE-buffered fragments => ~110 regs, fits 128-reg cap at
//      2 CTAs/SM => 16 warps/SM (4/SMSP) for latency hiding.
//      KC=64, NSTAGE=3 (108KB smem), one barrier per chunk.
//      convert_a (MLP=4) + convert_w merged into ONE kernel launch.
// ============================================================================

static constexpr int MDIM = 8;
static constexpr int BDIM = 4096;
static constexpr int DIN  = 512;
static constexpr int DOUT = 512;

static constexpr int BM = 128;
static constexpr int BN = 128;
static constexpr int KC = 64;              // K per pipeline chunk
static constexpr int NCHUNK = DIN / KC;    // 8
static constexpr int NSTAGE = 3;
static constexpr int THREADS = 256;        // 8 warps, 2x4 grid of 64x32 tiles

// SMEM rows: 64 halves (128B data) padded to 144B -> ldmatrix conflict-free,
// 16B-aligned for cp.async.
static constexpr int ROWB = 144;
static constexpr int A_REGION = BM * ROWB;             // 18432
static constexpr int B_REGION = BN * ROWB;             // 18432
static constexpr int STAGE_BYTES = A_REGION + B_REGION;    // 36864
static constexpr int SMEM_TOTAL  = NSTAGE * STAGE_BYTES;   // 110592

// fp16 scratch (static device globals; no runtime allocation)
__device__ __align__(16) __half g_Ah[(size_t)MDIM * BDIM * DIN];   // 32 MB
__device__ __align__(16) __half g_Bh[(size_t)MDIM * DOUT * DIN];   // 4 MB

// ---------------- helpers ----------------

__device__ __forceinline__ uint32_t smem_u32(const void* p) {
    uint32_t a;
    asm("{ .reg .u64 t; cvta.to.shared.u64 t, %1; cvt.u32.u64 %0, t; }"
        : "=r"(a) : "l"(p));
    return a;
}

__device__ __forceinline__ void cp16(uint32_t dst, const void* src) {
    asm volatile("cp.async.cg.shared.global [%0], [%1], 16;"
                 :: "r"(dst), "l"(src) : "memory");
}

__device__ __forceinline__ void ldmx4(uint32_t* r, uint32_t addr) {
    asm volatile("ldmatrix.sync.aligned.m8n8.x4.shared.b16 {%0,%1,%2,%3}, [%4];"
                 : "=r"(r[0]), "=r"(r[1]), "=r"(r[2]), "=r"(r[3]) : "r"(addr));
}

__device__ __forceinline__ void mma_f16(float* c, const uint32_t* a,
                                        const uint32_t* b) {
    asm volatile(
        "mma.sync.aligned.m16n8k16.row.col.f32.f16.f16.f32 "
        "{%0,%1,%2,%3}, {%4,%5,%6,%7}, {%8,%9}, {%0,%1,%2,%3};"
        : "+f"(c[0]), "+f"(c[1]), "+f"(c[2]), "+f"(c[3])
        : "r"(a[0]), "r"(a[1]), "r"(a[2]), "r"(a[3]),
          "r"(b[0]), "r"(b[1]));
}

// ---------------- merged preprocessing kernel ----------------
// blocks [0, A_BLOCKS): inp fp32 -> g_Ah fp16 (MLP=4)
// blocks [A_BLOCKS, A_BLOCKS + W_BLOCKS): w[m][i][o] -> g_Bh[m][o][i] fp16

static constexpr unsigned A_BLOCKS = (unsigned)((size_t)MDIM * BDIM * DIN / 4 / 1024); // 4096
static constexpr unsigned W_BLOCKS = (unsigned)(MDIM * (DIN / 32) * (DOUT / 32));      // 2048

__global__ void __launch_bounds__(256)
convert_all_kernel(const float4* __restrict__ inA, const float* __restrict__ w) {
    if (blockIdx.x < A_BLOCKS) {
        const size_t base = (size_t)blockIdx.x * 1024 + threadIdx.x;
        float4 v[4];
#pragma unroll
        for (int k = 0; k < 4; ++k) v[k] = inA[base + k * 256];
#pragma unroll
        for (int k = 0; k < 4; ++k) {
            __half2 h0 = __floats2half2_rn(v[k].x, v[k].y);
            __half2 h1 = __floats2half2_rn(v[k].z, v[k].w);
            uint2 st;
            st.x = *reinterpret_cast<uint32_t*>(&h0);
            st.y = *reinterpret_cast<uint32_t*>(&h1);
            reinterpret_cast<uint2*>(g_Ah)[base + k * 256] = st;
        }
    } else {
        __shared__ float tile[32][33];
        const unsigned wb = blockIdx.x - A_BLOCKS;       // 0..2047
        const int m  = (int)(wb >> 8);                   // 0..7
        const unsigned rem = wb & 255u;
        const int o0 = (int)(rem & 15u) * 32;
        const int i0 = (int)(rem >> 4) * 32;
        const int tx = threadIdx.x & 31;
        const int ty = threadIdx.x >> 5;                 // 0..7
        const float* wm = w + (size_t)m * DIN * DOUT;
        __half* bm = g_Bh + (size_t)m * DOUT * DIN;
#pragma unroll
        for (int j = 0; j < 32; j += 8)
            tile[ty + j][tx] = wm[(size_t)(i0 + ty + j) * DOUT + o0 + tx];
        __syncthreads();
#pragma unroll
        for (int j = 0; j < 32; j += 8)
            bm[(size_t)(o0 + ty + j) * DIN + i0 + tx] =
                __float2half_rn(tile[tx][ty + j]);
    }
}

// ---------------- main GEMM kernel ----------------

__global__ void __launch_bounds__(THREADS, 2)
fused_gemm_f16_kernel(const float* __restrict__ bias, float* __restrict__ out) {
    extern __shared__ char smem[];
    const uint32_t sbase = smem_u32(smem);

    const int tid  = threadIdx.x;
    const int warp = tid >> 5;
    const int lane = tid & 31;
    const int gid  = lane >> 2;
    const int tig  = lane & 3;
    const int wr   = warp >> 2;      // warp row (0..1) -> 64 rows
    const int wc   = warp & 3;       // warp col (0..3) -> 32 cols

    const int tn = blockIdx.x;       // D_OUT tile (0..3) — fastest: A reuse in L2
    const int tm = blockIdx.y;       // B-dim tile (0..31)
    const int mm = blockIdx.z;       // matrix (0..7)

    const __half* __restrict__ Ag = g_Ah + ((size_t)mm * BDIM + (size_t)tm * BM) * DIN;
    const __half* __restrict__ Bg = g_Bh + ((size_t)mm * DOUT + (size_t)tn * BN) * DIN;

    float acc[4][4][4];
#pragma unroll
    for (int mt = 0; mt < 4; ++mt)
#pragma unroll
        for (int nt = 0; nt < 4; ++nt)
#pragma unroll
            for (int i = 0; i < 4; ++i) acc[mt][nt][i] = 0.0f;

    // ---- async loader for chunk c into stage s: A 128x64h, B 128x64h
    auto issue_chunk = [&](int c, int s) {
        const uint32_t sA = sbase + s * STAGE_BYTES;
        const uint32_t sB = sA + A_REGION;
#pragma unroll
        for (int it = 0; it < 4; ++it) {
            int idx = tid + it * THREADS;        // 0..1023
            int row = idx >> 3;                  // 0..127
            int q   = idx & 7;                   // 16B eighth of 128B row
            cp16(sA + row * ROWB + q * 16, Ag + (size_t)row * DIN + c * KC + q * 8);
        }
#pragma unroll
        for (int it = 0; it < 4; ++it) {
            int idx = tid + it * THREADS;
            int n = idx >> 3;
            int q = idx & 7;
            cp16(sB + n * ROWB + q * 16, Bg + (size_t)n * DIN + c * KC + q * 8);
        }
        asm volatile("cp.async.commit_group;" ::: "memory");
    };

    // ---- per-lane ldmatrix base offsets (stage-relative)
    // A x4 tile mt: rows wr*64 + mt*16 + (l&15), colByte (l>>4)*16
    const uint32_t a_lane_off =
        (uint32_t)((wr * 64 + (lane & 15)) * ROWB + (lane >> 4) * 16);
    // B x4 pair p (n8-tiles 2p,2p+1): rows wc*32 + p*16 + (l&7) + ((l>>4)<<3)
    const uint32_t b_lane_off =
        (uint32_t)((wc * 32 + (lane & 7) + ((lane >> 4) << 3)) * ROWB +
                   ((lane >> 3) & 1) * 16);

    // ---- prologue: 2 chunks in flight
    issue_chunk(0, 0);
    issue_chunk(1, 1);

    // ---- main loop: one barrier per chunk; single-buffered fragments
#pragma unroll 1
    for (int c = 0; c < NCHUNK; ++c) {
        if (c < NCHUNK - 1)
            asm volatile("cp.async.wait_group 1;" ::: "memory");
        else
            asm volatile("cp.async.wait_group 0;" ::: "memory");
        __syncthreads();   // chunk c visible; all warps done with stage c-1

        const uint32_t sA = sbase + (c % NSTAGE) * STAGE_BYTES;
        const uint32_t sB = sA + A_REGION;

        // refill stage freed by chunk c-1 while we compute
        if (c + 2 < NCHUNK)
            issue_chunk(c + 2, (c + 2) % NSTAGE);

#pragma unroll
        for (int ks = 0; ks < 4; ++ks) {
            const uint32_t ko = (uint32_t)ks * 32;   // 16 halves = 32B
            uint32_t af[4][4], bf[2][4];
#pragma unroll
            for (int mt = 0; mt < 4; ++mt)
                ldmx4(af[mt], sA + a_lane_off + mt * (16 * ROWB) + ko);
#pragma unroll
            for (int p = 0; p < 2; ++p)
                ldmx4(bf[p], sB + b_lane_off + p * (16 * ROWB) + ko);
#pragma unroll
            for (int mt = 0; mt < 4; ++mt)
#pragma unroll
                for (int nt = 0; nt < 4; ++nt)
                    mma_f16(acc[mt][nt], af[mt], &bf[nt >> 1][(nt & 1) * 2]);
        }
    }

    // ---- epilogue: bias + relu, float2 stores
    const float* brow = bias + (size_t)mm * DOUT + tn * BN + wc * 32;
    float2 bv[4];
#pragma unroll
    for (int nt = 0; nt < 4; ++nt)
        bv[nt] = *reinterpret_cast<const float2*>(brow + nt * 8 + tig * 2);

#pragma unroll
    for (int mt = 0; mt < 4; ++mt) {
        const int r0 = tm * BM + wr * 64 + mt * 16 + gid;
        float* o0 = out + ((size_t)mm * BDIM + r0) * DOUT + tn * BN + wc * 32;
        float* o1 = o0 + 8 * DOUT;
#pragma unroll
        for (int nt = 0; nt < 4; ++nt) {
            float2 v0, v1;
            v0.x = fmaxf(acc[mt][nt][0] + bv[nt].x, 0.0f);
            v0.y = fmaxf(acc[mt][nt][1] + bv[nt].y, 0.0f);
            v1.x = fmaxf(acc[mt][nt][2] + bv[nt].x, 0.0f);
            v1.y = fmaxf(acc[mt][nt][3] + bv[nt].y, 0.0f);
            *reinterpret_cast<float2*>(o0 + nt * 8 + tig * 2) = v0;
            *reinterpret_cast<float2*>(o1 + nt * 8 + tig * 2) = v1;
        }
    }
}

// ---------------------------------------------------------------------------

extern "C" void kernel_launch(void* const* d_in, const int* in_sizes, int n_in,
                              void* d_out, int out_size) {
    const float* inp  = (const float*)d_in[0];   // [8, 4096, 512]
    const float* w    = (const float*)d_in[1];   // [8, 512, 512]
    const float* bias = (const float*)d_in[2];   // [8, 512]
    float* out = (float*)d_out;                  // [8, 4096, 512]
    (void)in_sizes; (void)n_in; (void)out_size;

    // 1) merged fp32 -> fp16 conversions (A same layout; W -> [m][o][i])
    convert_all_kernel<<<A_BLOCKS + W_BLOCKS, 256>>>((const float4*)inp, w);

    // 2) fp16 tensor-core GEMM + bias + relu
    cudaFuncSetAttribute(fused_gemm_f16_kernel,
                         cudaFuncAttributeMaxDynamicSharedMemorySize, SMEM_TOTAL);
    dim3 grid(DOUT / BN, BDIM / BM, MDIM);   // (4, 32, 8) = 1024 CTAs
    fused_gemm_f16_kernel<<<grid, THREADS, SMEM_TOTAL>>>(bias, out);
}